// round 13
// baseline (speedup 1.0000x reference)
#include <cuda_runtime.h>
#include <cuda_fp16.h>
#include <cstdint>

#define NM 256
#define NL 4
#define TILE_M 128
#define NTHREADS 512
#define LO_INV (1.0f / 1024.0f)

// Weights: hi = fp16(W)*1024 (exact pow2 scale), lo8 = e4m3((W - fp16(W))*1024).
__device__ __half  g_Bc[NL][256][64];
__device__ uint8_t g_Bc8[NL][256][64];
__device__ __half  g_W1[256][64];
__device__ uint8_t g_W18[256][64];
__device__ float g_lwv[NL][NM];

// ---------------------------------------------------------------------------
__device__ __forceinline__ uint32_t smem_u32(const void* p) {
    uint32_t a;
    asm("{ .reg .u64 t; cvta.to.shared.u64 t, %1; cvt.u32.u64 %0, t; }"
        : "=r"(a) : "l"(p));
    return a;
}
__device__ __forceinline__ float lds_f(uint32_t a) {
    float v; asm volatile("ld.shared.f32 %0, [%1];" : "=f"(v) : "r"(a)); return v;
}
__device__ __forceinline__ uint32_t lds_u32(uint32_t a) {
    uint32_t v; asm volatile("ld.shared.b32 %0, [%1];" : "=r"(v) : "r"(a)); return v;
}
__device__ __forceinline__ uint16_t lds_u16(uint32_t a) {
    uint16_t v; asm volatile("ld.shared.u16 %0, [%1];" : "=h"(v) : "r"(a)); return v;
}
__device__ __forceinline__ void sts_f(uint32_t a, float v) {
    asm volatile("st.shared.f32 [%0], %1;" :: "r"(a), "f"(v) : "memory");
}
__device__ __forceinline__ void sts_u32(uint32_t a, uint32_t v) {
    asm volatile("st.shared.b32 [%0], %1;" :: "r"(a), "r"(v) : "memory");
}
__device__ __forceinline__ void sts_u16(uint32_t a, uint16_t v) {
    asm volatile("st.shared.b16 [%0], %1;" :: "r"(a), "h"(v) : "memory");
}
__device__ __forceinline__ void sts_u8(uint32_t a, uint16_t v) {
    asm volatile("st.shared.b8 [%0], %1;" :: "r"(a), "h"(v) : "memory");
}
__device__ __forceinline__ void ldm_x4(uint32_t r[4], uint32_t addr) {
    asm volatile("ldmatrix.sync.aligned.m8n8.x4.shared.b16 {%0,%1,%2,%3}, [%4];"
                 : "=r"(r[0]), "=r"(r[1]), "=r"(r[2]), "=r"(r[3]) : "r"(addr));
}
__device__ __forceinline__ void mma16816(float c[4], const uint32_t a[4],
                                         uint32_t b0, uint32_t b1) {
    asm volatile("mma.sync.aligned.m16n8k16.row.col.f32.f16.f16.f32 "
                 "{%0,%1,%2,%3}, {%4,%5,%6,%7}, {%8,%9}, {%0,%1,%2,%3};"
                 : "+f"(c[0]), "+f"(c[1]), "+f"(c[2]), "+f"(c[3])
                 : "r"(a[0]), "r"(a[1]), "r"(a[2]), "r"(a[3]), "r"(b0), "r"(b1));
}
// fp8 e4m3 MMA, K=32, f32 accumulate
__device__ __forceinline__ void mma16832q(float c[4], const uint32_t a[4],
                                          uint32_t b0, uint32_t b1) {
    asm volatile("mma.sync.aligned.m16n8k32.row.col.f32.e4m3.e4m3.f32 "
                 "{%0,%1,%2,%3}, {%4,%5,%6,%7}, {%8,%9}, {%0,%1,%2,%3};"
                 : "+f"(c[0]), "+f"(c[1]), "+f"(c[2]), "+f"(c[3])
                 : "r"(a[0]), "r"(a[1]), "r"(a[2]), "r"(a[3]), "r"(b0), "r"(b1));
}
// pack two f32 -> e4m3x2 (.b16 dest: hi -> upper byte, lo -> lower byte)
__device__ __forceinline__ uint16_t f32x2_e4m3(float hi, float lo) {
    uint16_t p;
    asm("cvt.rn.satfinite.e4m3x2.f32 %0, %1, %2;" : "=h"(p) : "f"(hi), "f"(lo));
    return p;
}
__device__ __forceinline__ float hfu(uint16_t u) {
    return __half2float(__ushort_as_half(u));
}
#define CP_WAIT0() asm volatile("cp.async.wait_group 0;" ::: "memory")

// ---------------------------------------------------------------------------
__global__ void build_mats(const float* __restrict__ fw,
                           const float* __restrict__ lw) {
    const int l = blockIdx.x;
    const int kk = threadIdx.x;
    __shared__ float ks[NM];

    const float* fwl = fw + l * (NM / 2 + 1);
    float s = fwl[0];
    #pragma unroll 4
    for (int m = 1; m < NM / 2; ++m)
        s += 2.0f * fwl[m] * cospif((float)(m * kk) * (1.0f / 128.0f));
    s += fwl[NM / 2] * ((kk & 1) ? -1.0f : 1.0f);
    ks[kk] = s * (1.0f / 256.0f);
    if (blockIdx.y == 0) g_lwv[l][kk] = lw[l * NM + kk];
    __syncthreads();

    const int m0 = blockIdx.y * 32;
    for (int idx = kk; idx < 32 * 64; idx += 256) {
        int m = m0 + (idx >> 6), j = idx & 63;
        float v = ks[(m - j - 3) & (NM - 1)];
        __half hb = __float2half_rn(v);
        g_Bc[l][m][j] = __float2half_rn(__half2float(hb) * 1024.0f);
        g_Bc8[l][m][j] =
            (uint8_t)f32x2_e4m3(0.f, (v - __half2float(hb)) * 1024.0f);
    }
}

__global__ void enc_split(const float* __restrict__ W1) {
    int i = blockIdx.x * 256 + threadIdx.x;
    int n = i >> 6, k = i & 63;
    float v = W1[k * NM + n];
    __half hb = __float2half_rn(v);
    g_W1[n][k] = __float2half_rn(__half2float(hb) * 1024.0f);
    g_W18[n][k] = (uint8_t)f32x2_e4m3(0.f, (v - __half2float(hb)) * 1024.0f);
}

// ---------------------------------------------------------------------------
#define A_ST 512
#define OFF_A   0u          // 128 x 512B fp16 activations
#define OFF_A8  65536u      // 128 x 256B e4m3 activations
#define OFF_B0  98304u      // hi fp16 tall tile 256x128B
#define OFF_B8  131072u     // lo e4m3 tall tile 256x80B (stride-80, conflict-free)
#define OFF_LW  151552u
#define OFF_BB  152576u
#define OFF_W2  153600u
#define OFF_X   154624u
#define OFF_HS  156672u
#define OFF_PS  158720u
#define SMEM_TOTAL 160768

__device__ __forceinline__ void load_tile(const __half* g, uint32_t sbuf,
                                          int tid) {
    #pragma unroll
    for (int it = 0; it < 4; ++it) {
        int idx = it * NTHREADS + tid;
        int row = idx >> 3, seg = idx & 7;
        const void* src = g + row * 64 + seg * 8;
        uint32_t dst = sbuf + row * 128 + ((seg * 16) ^ ((row & 7) * 16));
        asm volatile("cp.async.cg.shared.global [%0], [%1], 16;"
                     :: "r"(dst), "l"(src) : "memory");
    }
    asm volatile("cp.async.commit_group;" ::: "memory");
}
__device__ __forceinline__ void load_tile8(const uint8_t* g, uint32_t sbuf,
                                           int tid) {
    #pragma unroll
    for (int it = 0; it < 2; ++it) {
        int idx = it * NTHREADS + tid;
        int row = idx >> 2, seg = idx & 3;
        const void* src = g + row * 64 + seg * 16;
        uint32_t dst = sbuf + row * 80 + seg * 16;
        asm volatile("cp.async.cg.shared.global [%0], [%1], 16;"
                     :: "r"(dst), "l"(src) : "memory");
    }
    asm volatile("cp.async.commit_group;" ::: "memory");
}

// ---------------------------------------------------------------------------
__global__ __launch_bounds__(NTHREADS, 1)
void fno_mma(const float* __restrict__ mu, const float* __restrict__ x,
             const float* __restrict__ b1, const float* __restrict__ b2,
             const float* __restrict__ W2, float* __restrict__ out) {
    extern __shared__ __align__(16) unsigned char smraw[];
    const uint32_t sb = smem_u32(smraw);

    const int tid = threadIdx.x;
    const int lane = tid & 31, wid = tid >> 5;
    const int wm = wid >> 2, wn = wid & 3;       // 4x4 warp grid, 32x64 tiles
    const int g = lane >> 2, qi = lane & 3;
    const int r8 = lane & 7, q = lane >> 3;
    const long long row0 = (long long)blockIdx.x * TILE_M;

    const int rA0 = wm * 32 + r8 + (q & 1) * 8;
    const uint32_t swA = (uint32_t)(rA0 & 7) * 16;
    const int rB0 = wn * 64 + r8 + (q & 1) * 8;
    const uint32_t swB = (uint32_t)(rB0 & 7) * 16;
    const uint32_t cB16 = (uint32_t)(q >> 1) * 16;

    // kick encoder weight tiles
    load_tile(&g_W1[0][0], sb + OFF_B0, tid);
    load_tile8(&g_W18[0][0], sb + OFF_B8, tid);

    // stage scalars
    if (tid < 256) {
        sts_f(sb + OFF_BB + tid * 4, b1[tid]);
        sts_f(sb + OFF_W2 + tid * 4, W2[tid]);
    }
    for (int i = tid; i < TILE_M * 3; i += NTHREADS) {
        int r = i / 3, c = i % 3;
        sts_f(sb + OFF_X + (r * 3 + c) * 4, x[(row0 + r) * 3 + c]);
    }
    // stage mu: fp16 into A, e4m3 into A8
    {
        const float2* mu2 = (const float2*)(mu + row0 * 64);
        for (int i = tid; i < TILE_M * 32; i += NTHREADS) {
            int r = i >> 5, c2 = i & 31;
            float2 v = mu2[r * 32 + c2];
            const uint32_t swr = (uint32_t)(r & 7) * 16;
            uint16_t h0 = __half_as_ushort(__float2half_rn(v.x));
            uint16_t h1 = __half_as_ushort(__float2half_rn(v.y));
            sts_u32(sb + OFF_A + (uint32_t)r * A_ST + (((uint32_t)c2 * 4) ^ swr),
                    (uint32_t)h0 | ((uint32_t)h1 << 16));
            sts_u16(sb + OFF_A8 + (uint32_t)r * 256 + (((uint32_t)c2 * 2) ^ swr),
                    f32x2_e4m3(v.y, v.x));
        }
    }

    float cH[2][8][4];
    float dacc[2][2];

    for (int st = 0; st < 5; ++st) {
        const bool enc = (st == 0), dec = (st == 4);
        const int l = st - 1;

        CP_WAIT0();
        __syncthreads();
        if (!enc && tid < 256) sts_f(sb + OFF_LW + tid * 4, g_lwv[l][tid]);

        #pragma unroll
        for (int mt = 0; mt < 2; ++mt)
            #pragma unroll
            for (int nt = 0; nt < 8; ++nt)
                #pragma unroll
                for (int e = 0; e < 4; ++e) cH[mt][nt][e] = 0.f;
        if (dec) {
            #pragma unroll
            for (int mt = 0; mt < 2; ++mt) dacc[mt][0] = dacc[mt][1] = 0.f;
        }

        const int ns = enc ? 1 : 4;
        for (int s = 0; s < ns; ++s) {
            const int rBs = (rB0 - 64 * s) & 255;
            const uint32_t aCol0 = (uint32_t)s * 128 + cB16;
            // ---- hi term: fp16 K=16 ----
            #pragma unroll
            for (int kc = 0; kc < 4; ++kc) {
                const uint32_t aCsw = ((aCol0 + kc * 32) ^ swA);
                const uint32_t bCsw = (((uint32_t)kc * 32 + cB16) ^ swB);
                uint32_t aF[2][4], bf[4][4];
                #pragma unroll
                for (int mt = 0; mt < 2; ++mt)
                    ldm_x4(aF[mt], sb + OFF_A + (uint32_t)(rA0 + mt * 16) * A_ST + aCsw);
                #pragma unroll
                for (int np = 0; np < 4; ++np) {
                    uint32_t ro = (uint32_t)(((rBs + np * 16) & 255)) * 128;
                    ldm_x4(bf[np], sb + OFF_B0 + ro + bCsw);
                }
                #pragma unroll
                for (int mt = 0; mt < 2; ++mt)
                    #pragma unroll
                    for (int np = 0; np < 4; ++np) {
                        mma16816(cH[mt][2 * np],     aF[mt], bf[np][0], bf[np][2]);
                        mma16816(cH[mt][2 * np + 1], aF[mt], bf[np][1], bf[np][3]);
                    }
            }
            // ---- lo term: e4m3 K=32 ----
            #pragma unroll
            for (int kc32 = 0; kc32 < 2; ++kc32) {
                const uint32_t a8Csw = (((uint32_t)s * 64 + kc32 * 32 + cB16) ^ swA);
                uint32_t a8F[2][4];
                #pragma unroll
                for (int mt = 0; mt < 2; ++mt)
                    ldm_x4(a8F[mt], sb + OFF_A8 + (uint32_t)(rA0 + mt * 16) * 256 + a8Csw);
                #pragma unroll
                for (int np = 0; np < 4; ++np) {
                    uint32_t ro8 = (uint32_t)(((rBs + np * 16) & 255)) * 80;
                    uint32_t bf[4];
                    ldm_x4(bf, sb + OFF_B8 + ro8 + kc32 * 32 + cB16);
                    mma16832q(cH[0][2 * np],     a8F[0], bf[0], bf[2]);
                    mma16832q(cH[0][2 * np + 1], a8F[0], bf[1], bf[3]);
                    mma16832q(cH[1][2 * np],     a8F[1], bf[0], bf[2]);
                    mma16832q(cH[1][2 * np + 1], a8F[1], bf[1], bf[3]);
                }
            }
        }
        __syncthreads();

        if (st < 4) {   // prefetch next layer's tiles
            load_tile(&g_Bc[st][0][0], sb + OFF_B0, tid);
            load_tile8(&g_Bc8[st][0][0], sb + OFF_B8, tid);
        }

        // -------- epilogue --------
        #pragma unroll
        for (int nt = 0; nt < 8; ++nt) {
            const int c0 = wn * 64 + nt * 8 + qi * 2;
            float lw0 = 0.f, lw1 = 0.f, bb0 = 0.f, bb1 = 0.f, w0 = 0.f, w1 = 0.f;
            if (enc) {
                bb0 = lds_f(sb + OFF_BB + c0 * 4);
                bb1 = lds_f(sb + OFF_BB + c0 * 4 + 4);
            } else {
                lw0 = lds_f(sb + OFF_LW + c0 * 4);
                lw1 = lds_f(sb + OFF_LW + c0 * 4 + 4);
            }
            if (dec) {
                w0 = lds_f(sb + OFF_W2 + c0 * 4);
                w1 = lds_f(sb + OFF_W2 + c0 * 4 + 4);
            }
            #pragma unroll
            for (int mt = 0; mt < 2; ++mt)
                #pragma unroll
                for (int h = 0; h < 2; ++h) {
                    const int r = wm * 32 + mt * 16 + g + h * 8;
                    const uint32_t swr = (uint32_t)(r & 7) * 16;
                    const uint32_t rbase = (uint32_t)r * A_ST;
                    const uint32_t rbase8 = (uint32_t)r * 256;
                    float v0 = cH[mt][nt][2 * h] * LO_INV;
                    float v1 = cH[mt][nt][2 * h + 1] * LO_INV;

                    if (enc) {
                        v0 += bb0; v1 += bb1;
                    } else {
                        float hp0, hp1;
                        if (c0 < 252) {
                            uint32_t uh = lds_u32(sb + OFF_A + rbase + (((uint32_t)c0 * 2) ^ swr));
                            hp0 = hfu((uint16_t)uh);
                            hp1 = hfu((uint16_t)(uh >> 16));
                        } else {
                            hp0 = (c0 < 253)
                                ? hfu(lds_u16(sb + OFF_A + rbase + (((uint32_t)c0 * 2) ^ swr)))
                                : lds_f(sb + OFF_HS + (r * 3 + c0 - 253) * 4);
                            hp1 = (c0 + 1 < 253)
                                ? 0.f
                                : lds_f(sb + OFF_HS + (r * 3 + c0 + 1 - 253) * 4);
                        }
                        v0 += lw0 * hp0; v1 += lw1 * hp1;
                    }
                    v0 = fmaxf(v0, 0.f); v1 = fmaxf(v1, 0.f);

                    if (dec) {
                        dacc[mt][h] += v0 * w0 + v1 * w1;
                    } else if (c0 < 252) {
                        uint16_t h0 = __half_as_ushort(__float2half_rn(v0));
                        uint16_t h1 = __half_as_ushort(__float2half_rn(v1));
                        sts_u32(sb + OFF_A + rbase + (((uint32_t)c0 * 2) ^ swr),
                                (uint32_t)h0 | ((uint32_t)h1 << 16));
                        sts_u16(sb + OFF_A8 + rbase8 + (((uint32_t)c0) ^ swr),
                                f32x2_e4m3(v1, v0));
                    } else {
                        #pragma unroll
                        for (int e = 0; e < 2; ++e) {
                            int n = c0 + e;
                            float v = e ? v1 : v0;
                            if (n < 253) {
                                sts_u16(sb + OFF_A + rbase + (((uint32_t)n * 2) ^ swr),
                                        __half_as_ushort(__float2half_rn(v)));
                                sts_u8(sb + OFF_A8 + rbase8 + (((uint32_t)n) ^ swr),
                                       f32x2_e4m3(0.f, v));
                            } else {
                                sts_f(sb + OFF_HS + (r * 3 + n - 253) * 4, v);
                                if (enc) {
                                    float xv = lds_f(sb + OFF_X + (r * 3 + n - 253) * 4);
                                    sts_u16(sb + OFF_A + rbase + (((uint32_t)n * 2) ^ swr),
                                            __half_as_ushort(__float2half_rn(xv)));
                                    sts_u8(sb + OFF_A8 + rbase8 + (((uint32_t)n) ^ swr),
                                           f32x2_e4m3(0.f, xv));
                                }
                            }
                        }
                    }
                }
        }

        if (dec) {
            #pragma unroll
            for (int mt = 0; mt < 2; ++mt)
                #pragma unroll
                for (int h = 0; h < 2; ++h) {
                    float s = dacc[mt][h];
                    s += __shfl_xor_sync(0xffffffffu, s, 1);
                    s += __shfl_xor_sync(0xffffffffu, s, 2);
                    if (qi == 0) {
                        int r = wm * 32 + mt * 16 + g + h * 8;
                        sts_f(sb + OFF_PS + r * 16 + wn * 4, s);
                    }
                }
            __syncthreads();
            if (tid < TILE_M) {
                float o = lds_f(sb + OFF_PS + tid * 16)
                        + lds_f(sb + OFF_PS + tid * 16 + 4)
                        + lds_f(sb + OFF_PS + tid * 16 + 8)
                        + lds_f(sb + OFF_PS + tid * 16 + 12);
                out[row0 + tid] = o + b2[0];
            }
        }
    }
}

// ---------------------------------------------------------------------------
extern "C" void kernel_launch(void* const* d_in, const int* in_sizes, int n_in,
                              void* d_out, int out_size) {
    const float* mu = (const float*)d_in[0];
    const float* x  = (const float*)d_in[1];
    const float* W1 = (const float*)d_in[2];
    const float* b1 = (const float*)d_in[3];
    const float* fw = (const float*)d_in[4];
    const float* lw = (const float*)d_in[5];
    const float* W2 = (const float*)d_in[6];
    const float* b2 = (const float*)d_in[7];
    float* out = (float*)d_out;

    const int B = in_sizes[0] / 64;

    build_mats<<<dim3(NL, 8), NM>>>(fw, lw);
    enc_split<<<64, 256>>>(W1);

    cudaFuncSetAttribute(fno_mma, cudaFuncAttributeMaxDynamicSharedMemorySize,
                         SMEM_TOTAL);
    fno_mma<<<B / TILE_M, NTHREADS, SMEM_TOTAL>>>(mu, x, b1, b2, W2, out);
}

// round 14
// speedup vs baseline: 1.8407x; 1.8407x over previous
#include <cuda_runtime.h>
#include <cuda_fp16.h>
#include <cstdint>

#define NM 256
#define NL 4
#define TILE_M 128
#define NTHREADS 512

// Circulant tall tiles Btall[m][j] = fp16(c[(m-j-3)&255]).
__device__ __half g_Bc[NL][256][64];
__device__ __half g_W1[256][64];
__device__ float g_lwv[NL][NM];

// ---------------------------------------------------------------------------
__device__ __forceinline__ uint32_t smem_u32(const void* p) {
    uint32_t a;
    asm("{ .reg .u64 t; cvta.to.shared.u64 t, %1; cvt.u32.u64 %0, t; }"
        : "=r"(a) : "l"(p));
    return a;
}
__device__ __forceinline__ float lds_f(uint32_t a) {
    float v; asm volatile("ld.shared.f32 %0, [%1];" : "=f"(v) : "r"(a)); return v;
}
__device__ __forceinline__ uint32_t lds_u32(uint32_t a) {
    uint32_t v; asm volatile("ld.shared.b32 %0, [%1];" : "=r"(v) : "r"(a)); return v;
}
__device__ __forceinline__ uint16_t lds_u16(uint32_t a) {
    uint16_t v; asm volatile("ld.shared.u16 %0, [%1];" : "=h"(v) : "r"(a)); return v;
}
__device__ __forceinline__ void sts_f(uint32_t a, float v) {
    asm volatile("st.shared.f32 [%0], %1;" :: "r"(a), "f"(v) : "memory");
}
__device__ __forceinline__ void sts_u32(uint32_t a, uint32_t v) {
    asm volatile("st.shared.b32 [%0], %1;" :: "r"(a), "r"(v) : "memory");
}
__device__ __forceinline__ void sts_u16(uint32_t a, uint16_t v) {
    asm volatile("st.shared.b16 [%0], %1;" :: "r"(a), "h"(v) : "memory");
}
__device__ __forceinline__ void ldm_x4(uint32_t r[4], uint32_t addr) {
    asm volatile("ldmatrix.sync.aligned.m8n8.x4.shared.b16 {%0,%1,%2,%3}, [%4];"
                 : "=r"(r[0]), "=r"(r[1]), "=r"(r[2]), "=r"(r[3]) : "r"(addr));
}
__device__ __forceinline__ void mma16816(float c[4], const uint32_t a[4],
                                         uint32_t b0, uint32_t b1) {
    asm volatile("mma.sync.aligned.m16n8k16.row.col.f32.f16.f16.f32 "
                 "{%0,%1,%2,%3}, {%4,%5,%6,%7}, {%8,%9}, {%0,%1,%2,%3};"
                 : "+f"(c[0]), "+f"(c[1]), "+f"(c[2]), "+f"(c[3])
                 : "r"(a[0]), "r"(a[1]), "r"(a[2]), "r"(a[3]), "r"(b0), "r"(b1));
}
__device__ __forceinline__ float hfu(uint16_t u) {
    return __half2float(__ushort_as_half(u));
}
#define CP_WAIT0() asm volatile("cp.async.wait_group 0;" ::: "memory")

// ---------------------------------------------------------------------------
__global__ void build_mats(const float* __restrict__ fw,
                           const float* __restrict__ lw) {
    const int l = blockIdx.x;
    const int kk = threadIdx.x;
    __shared__ float ks[NM];

    const float* fwl = fw + l * (NM / 2 + 1);
    float s = fwl[0];
    #pragma unroll 4
    for (int m = 1; m < NM / 2; ++m)
        s += 2.0f * fwl[m] * cospif((float)(m * kk) * (1.0f / 128.0f));
    s += fwl[NM / 2] * ((kk & 1) ? -1.0f : 1.0f);
    ks[kk] = s * (1.0f / 256.0f);
    if (blockIdx.y == 0) g_lwv[l][kk] = lw[l * NM + kk];
    __syncthreads();

    const int m0 = blockIdx.y * 32;
    for (int idx = kk; idx < 32 * 64; idx += 256) {
        int m = m0 + (idx >> 6), j = idx & 63;
        g_Bc[l][m][j] = __float2half_rn(ks[(m - j - 3) & (NM - 1)]);
    }
}

__global__ void enc_split(const float* __restrict__ W1) {
    int i = blockIdx.x * 256 + threadIdx.x;
    int n = i >> 6, k = i & 63;
    g_W1[n][k] = __float2half_rn(W1[k * NM + n]);
}

// ---------------------------------------------------------------------------
#define A_ST 512
#define OFF_A  0u           // 128 x 512B fp16 activations
#define OFF_B0 65536u       // 256 x 128B fp16 circulant tall tile
#define OFF_LW 98304u
#define OFF_BB 99328u
#define OFF_W2 100352u
#define OFF_X  101376u
#define OFF_HS 103424u
#define OFF_PS 104960u
#define SMEM_TOTAL 107008

__device__ __forceinline__ void load_tile(const __half* g, uint32_t sbuf,
                                          int tid) {
    #pragma unroll
    for (int it = 0; it < 4; ++it) {
        int idx = it * NTHREADS + tid;
        int row = idx >> 3, seg = idx & 7;
        const void* src = g + row * 64 + seg * 8;
        uint32_t dst = sbuf + row * 128 + ((seg * 16) ^ ((row & 7) * 16));
        asm volatile("cp.async.cg.shared.global [%0], [%1], 16;"
                     :: "r"(dst), "l"(src) : "memory");
    }
    asm volatile("cp.async.commit_group;" ::: "memory");
}

// ---------------------------------------------------------------------------
__global__ __launch_bounds__(NTHREADS, 1)
void fno_mma(const float* __restrict__ mu, const float* __restrict__ x,
             const float* __restrict__ b1, const float* __restrict__ b2,
             const float* __restrict__ W2, float* __restrict__ out) {
    extern __shared__ __align__(16) unsigned char smraw[];
    const uint32_t sb = smem_u32(smraw);

    const int tid = threadIdx.x;
    const int lane = tid & 31, wid = tid >> 5;
    const int wm = wid >> 2, wn = wid & 3;       // 4x4 warp grid, 32x64 tiles
    const int g = lane >> 2, qi = lane & 3;
    const int r8 = lane & 7, q = lane >> 3;
    const long long row0 = (long long)blockIdx.x * TILE_M;

    const int rA0 = wm * 32 + r8 + (q & 1) * 8;
    const uint32_t swA = (uint32_t)(rA0 & 7) * 16;
    const int rB0 = wn * 64 + r8 + (q & 1) * 8;
    const uint32_t swB = (uint32_t)(rB0 & 7) * 16;
    const uint32_t cB16 = (uint32_t)(q >> 1) * 16;

    // kick encoder weight tile
    load_tile(&g_W1[0][0], sb + OFF_B0, tid);

    // stage scalars
    if (tid < 256) {
        sts_f(sb + OFF_BB + tid * 4, b1[tid]);
        sts_f(sb + OFF_W2 + tid * 4, W2[tid]);
    }
    for (int i = tid; i < TILE_M * 3; i += NTHREADS) {
        int r = i / 3, c = i % 3;
        sts_f(sb + OFF_X + (r * 3 + c) * 4, x[(row0 + r) * 3 + c]);
    }
    // stage mu (cols 0-63 of A, fp16)
    {
        const float2* mu2 = (const float2*)(mu + row0 * 64);
        for (int i = tid; i < TILE_M * 32; i += NTHREADS) {
            int r = i >> 5, c2 = i & 31;
            float2 v = mu2[r * 32 + c2];
            uint16_t h0 = __half_as_ushort(__float2half_rn(v.x));
            uint16_t h1 = __half_as_ushort(__float2half_rn(v.y));
            uint32_t off = (uint32_t)r * A_ST + ((uint32_t)(c2 * 4) ^ ((r & 7) * 16));
            sts_u32(sb + OFF_A + off, (uint32_t)h0 | ((uint32_t)h1 << 16));
        }
    }

    float c[2][8][4];
    float dacc[2][2];

    for (int st = 0; st < 5; ++st) {
        const bool enc = (st == 0), dec = (st == 4);
        const int l = st - 1;

        CP_WAIT0();
        __syncthreads();
        if (!enc && tid < 256) sts_f(sb + OFF_LW + tid * 4, g_lwv[l][tid]);

        #pragma unroll
        for (int mt = 0; mt < 2; ++mt)
            #pragma unroll
            for (int nt = 0; nt < 8; ++nt)
                #pragma unroll
                for (int e = 0; e < 4; ++e) c[mt][nt][e] = 0.f;
        if (dec) {
            #pragma unroll
            for (int mt = 0; mt < 2; ++mt) dacc[mt][0] = dacc[mt][1] = 0.f;
        }

        const int ns = enc ? 1 : 4;
        for (int s = 0; s < ns; ++s) {
            const int rBs = (rB0 - 64 * s) & 255;
            const uint32_t aCol0 = (uint32_t)s * 128 + cB16;
            #pragma unroll
            for (int kc = 0; kc < 4; ++kc) {
                const uint32_t aCsw = ((aCol0 + kc * 32) ^ swA);
                const uint32_t bCsw = (((uint32_t)kc * 32 + cB16) ^ swB);
                uint32_t aF[2][4];
                #pragma unroll
                for (int mt = 0; mt < 2; ++mt)
                    ldm_x4(aF[mt], sb + OFF_A + (uint32_t)(rA0 + mt * 16) * A_ST + aCsw);
                #pragma unroll
                for (int np = 0; np < 4; ++np) {
                    const uint32_t ro = (uint32_t)(((rBs + np * 16) & 255)) * 128;
                    uint32_t bf[4];
                    ldm_x4(bf, sb + OFF_B0 + ro + bCsw);
                    mma16816(c[0][2 * np],     aF[0], bf[0], bf[2]);
                    mma16816(c[0][2 * np + 1], aF[0], bf[1], bf[3]);
                    mma16816(c[1][2 * np],     aF[1], bf[0], bf[2]);
                    mma16816(c[1][2 * np + 1], aF[1], bf[1], bf[3]);
                }
            }
        }
        __syncthreads();

        if (st < 4) {   // prefetch next layer's circulant tile
            load_tile(&g_Bc[st][0][0], sb + OFF_B0, tid);
        }

        // -------- epilogue (each (r,n) owned by one thread) --------
        #pragma unroll
        for (int nt = 0; nt < 8; ++nt) {
            const int c0 = wn * 64 + nt * 8 + qi * 2;
            float lw0 = 0.f, lw1 = 0.f, bb0 = 0.f, bb1 = 0.f, w0 = 0.f, w1 = 0.f;
            if (enc) {
                bb0 = lds_f(sb + OFF_BB + c0 * 4);
                bb1 = lds_f(sb + OFF_BB + c0 * 4 + 4);
            } else {
                lw0 = lds_f(sb + OFF_LW + c0 * 4);
                lw1 = lds_f(sb + OFF_LW + c0 * 4 + 4);
            }
            if (dec) {
                w0 = lds_f(sb + OFF_W2 + c0 * 4);
                w1 = lds_f(sb + OFF_W2 + c0 * 4 + 4);
            }
            #pragma unroll
            for (int mt = 0; mt < 2; ++mt)
                #pragma unroll
                for (int h = 0; h < 2; ++h) {
                    const int r = wm * 32 + mt * 16 + g + h * 8;
                    const uint32_t swr = (uint32_t)(r & 7) * 16;
                    const uint32_t rbase = (uint32_t)r * A_ST;
                    float v0 = c[mt][nt][2 * h], v1 = c[mt][nt][2 * h + 1];

                    if (enc) {
                        v0 += bb0; v1 += bb1;
                    } else {
                        float hp0, hp1;
                        if (c0 < 252) {
                            uint32_t uh = lds_u32(sb + OFF_A + rbase + (((uint32_t)c0 * 2) ^ swr));
                            hp0 = hfu((uint16_t)uh);
                            hp1 = hfu((uint16_t)(uh >> 16));
                        } else {
                            hp0 = (c0 < 253)
                                ? hfu(lds_u16(sb + OFF_A + rbase + (((uint32_t)c0 * 2) ^ swr)))
                                : lds_f(sb + OFF_HS + (r * 3 + c0 - 253) * 4);
                            hp1 = (c0 + 1 < 253)
                                ? 0.f
                                : lds_f(sb + OFF_HS + (r * 3 + c0 + 1 - 253) * 4);
                        }
                        v0 += lw0 * hp0; v1 += lw1 * hp1;
                    }
                    v0 = fmaxf(v0, 0.f); v1 = fmaxf(v1, 0.f);

                    if (dec) {
                        dacc[mt][h] += v0 * w0 + v1 * w1;
                    } else if (c0 < 252) {
                        uint16_t h0 = __half_as_ushort(__float2half_rn(v0));
                        uint16_t h1 = __half_as_ushort(__float2half_rn(v1));
                        uint32_t off = rbase + (((uint32_t)c0 * 2) ^ swr);
                        sts_u32(sb + OFF_A + off, (uint32_t)h0 | ((uint32_t)h1 << 16));
                    } else {
                        #pragma unroll
                        for (int e = 0; e < 2; ++e) {
                            int n = c0 + e;
                            float v = e ? v1 : v0;
                            if (n < 253) {
                                uint32_t off = rbase + (((uint32_t)n * 2) ^ swr);
                                sts_u16(sb + OFF_A + off,
                                        __half_as_ushort(__float2half_rn(v)));
                            } else {
                                sts_f(sb + OFF_HS + (r * 3 + n - 253) * 4, v);
                                if (enc) {
                                    float xv = lds_f(sb + OFF_X + (r * 3 + n - 253) * 4);
                                    uint32_t off = rbase + (((uint32_t)n * 2) ^ swr);
                                    sts_u16(sb + OFF_A + off,
                                            __half_as_ushort(__float2half_rn(xv)));
                                }
                            }
                        }
                    }
                }
        }

        if (dec) {
            #pragma unroll
            for (int mt = 0; mt < 2; ++mt)
                #pragma unroll
                for (int h = 0; h < 2; ++h) {
                    float s = dacc[mt][h];
                    s += __shfl_xor_sync(0xffffffffu, s, 1);
                    s += __shfl_xor_sync(0xffffffffu, s, 2);
                    if (qi == 0) {
                        int r = wm * 32 + mt * 16 + g + h * 8;
                        sts_f(sb + OFF_PS + r * 16 + wn * 4, s);
                    }
                }
            __syncthreads();
            if (tid < TILE_M) {
                float o = lds_f(sb + OFF_PS + tid * 16)
                        + lds_f(sb + OFF_PS + tid * 16 + 4)
                        + lds_f(sb + OFF_PS + tid * 16 + 8)
                        + lds_f(sb + OFF_PS + tid * 16 + 12);
                out[row0 + tid] = o + b2[0];
            }
        }
    }
}

// ---------------------------------------------------------------------------
extern "C" void kernel_launch(void* const* d_in, const int* in_sizes, int n_in,
                              void* d_out, int out_size) {
    const float* mu = (const float*)d_in[0];
    const float* x  = (const float*)d_in[1];
    const float* W1 = (const float*)d_in[2];
    const float* b1 = (const float*)d_in[3];
    const float* fw = (const float*)d_in[4];
    const float* lw = (const float*)d_in[5];
    const float* W2 = (const float*)d_in[6];
    const float* b2 = (const float*)d_in[7];
    float* out = (float*)d_out;

    const int B = in_sizes[0] / 64;

    build_mats<<<dim3(NL, 8), NM>>>(fw, lw);
    enc_split<<<64, 256>>>(W1);

    cudaFuncSetAttribute(fno_mma, cudaFuncAttributeMaxDynamicSharedMemorySize,
                         SMEM_TOTAL);
    fno_mma<<<B / TILE_M, NTHREADS, SMEM_TOTAL>>>(mu, x, b1, b2, W2, out);
}